// round 5
// baseline (speedup 1.0000x reference)
#include <cuda_runtime.h>
#include <cstdint>

#define NUM_EMBED 8192
#define ED 64
#define NTOK 32768
#define CH_STRIDE 4096
#define B_STRIDE 262144

#define OFF_LOSS 2097152
#define OFF_IDX  2097153
#define OFF_BIN  (2097153 + 32768)

#define MCTA 32                      /* tokens per CTA */
#define NBLK (NTOK / MCTA)           /* 1024 */
#define KB 128                       /* codes per tile */
#define NTILES (NUM_EMBED / KB)      /* 64 */

__device__ float g_cnormT[ED * NUM_EMBED];  // [c][k] normalized codebook, transposed
__device__ float g_partial[NBLK];

typedef unsigned long long ull;

__device__ __forceinline__ void ffma2(ull &d, ull a, ull b) {
    asm("fma.rn.f32x2 %0, %1, %2, %0;" : "+l"(d) : "l"(a), "l"(b));
}
__device__ __forceinline__ float lo32(ull v) { return __uint_as_float((unsigned)(v & 0xFFFFFFFFULL)); }
__device__ __forceinline__ float hi32(ull v) { return __uint_as_float((unsigned)(v >> 32)); }
__device__ __forceinline__ uint32_t smem_u32(const void* p) {
    uint32_t a;
    asm("{ .reg .u64 t; cvta.to.shared.u64 t, %1; cvt.u32.u64 %0, t; }" : "=r"(a) : "l"(p));
    return a;
}
#define CP_ASYNC16(dst, src) asm volatile("cp.async.cg.shared.global [%0], [%1], 16;" :: "r"(dst), "l"(src))
#define CP_COMMIT()          asm volatile("cp.async.commit_group;" ::: "memory")
#define CP_WAIT0()           asm volatile("cp.async.wait_group 0;" ::: "memory")

// ---------------- K1: normalize codebook, store transposed [c][k] ----------------
__global__ void k1_normalize(const float* __restrict__ ew) {
    int k = blockIdx.x * blockDim.x + threadIdx.x;
    const float4* row = (const float4*)(ew + (size_t)k * ED);
    float4 v[16];
    float ss = 0.f;
#pragma unroll
    for (int i = 0; i < 16; ++i) {
        v[i] = row[i];
        ss = fmaf(v[i].x, v[i].x, ss);
        ss = fmaf(v[i].y, v[i].y, ss);
        ss = fmaf(v[i].z, v[i].z, ss);
        ss = fmaf(v[i].w, v[i].w, ss);
    }
    float dn = fmaxf(__fsqrt_rn(ss), 1e-12f);
#pragma unroll
    for (int i = 0; i < 16; ++i) {
        g_cnormT[(4 * i + 0) * NUM_EMBED + k] = __fdiv_rn(v[i].x, dn);
        g_cnormT[(4 * i + 1) * NUM_EMBED + k] = __fdiv_rn(v[i].y, dn);
        g_cnormT[(4 * i + 2) * NUM_EMBED + k] = __fdiv_rn(v[i].z, dn);
        g_cnormT[(4 * i + 3) * NUM_EMBED + k] = __fdiv_rn(v[i].w, dn);
    }
}

// ---------------- K2: fused normalize + GEMM-argmax + gather/STE/loss/idx/bin ----------------
// CTA: 32 tokens, 128 threads (4 warps); warp owns 8 tokens, lane owns 4 codes/tile.
#define SM_ZRAW 0                    /* 64*32*4   = 8192  raw z [c][t] */
#define SM_ZS2  8192                 /* 64*32*8   = 16384 normalized dup f32x2 [c][t] */
#define SM_NM   24576                /* 32*4 */
#define SM_IDXS 24704                /* 32*4 */
#define SM_RED  24832                /* 128*4 */
#define SM_WS0  25344                /* 64*128*4  = 32768 */
#define SM_WS1  (SM_WS0 + 32768)
#define SM_TOT  (SM_WS1 + 32768)     /* 90880 */

__global__ __launch_bounds__(128, 2) void k2_all(const float* __restrict__ z,
                                                 const float* __restrict__ ew,
                                                 float* __restrict__ out_zq,
                                                 float* __restrict__ out_idx,
                                                 float* __restrict__ out_bin) {
    extern __shared__ char sm_[];
    uint32_t sbase = smem_u32(sm_);
    float*  zraw = (float*)(sm_ + SM_ZRAW);
    float2* zs2  = (float2*)(sm_ + SM_ZS2);
    float*  nm   = (float*)(sm_ + SM_NM);
    int*    idxs = (int*)(sm_ + SM_IDXS);
    float*  red  = (float*)(sm_ + SM_RED);

    const int tid  = threadIdx.x;
    const int warp = tid >> 5;
    const int lane = tid & 31;

    const int tok0 = blockIdx.x * MCTA;
    const int b    = tok0 >> 12;
    const int p0   = tok0 & 4095;
    const float* zb = z + (size_t)b * B_STRIDE + p0;

    // prefetch codebook tile 0 first (overlaps z setup)
    for (int i = tid; i < 2048; i += 128) {
        int c = i >> 5, q = i & 31;
        CP_ASYNC16(sbase + SM_WS0 + (c * KB + q * 4) * 4,
                   (const char*)(g_cnormT + (size_t)c * NUM_EMBED) + q * 16);
    }
    CP_COMMIT();

    // load raw z tile [c][32]
    for (int i = tid; i < 512; i += 128) {
        int c = i >> 3, q = i & 7;
        float4 v = ((const float4*)(zb + c * CH_STRIDE))[q];
        ((float4*)(zraw + c * 32))[q] = v;
    }
    __syncthreads();

    // per-token norms (same op order as the passing R1 kernel)
    if (tid < 32) {
        float ss = 0.f;
        for (int c = 0; c < 64; ++c) {
            float x = zraw[c * 32 + tid];
            ss = fmaf(x, x, ss);
        }
        nm[tid] = fmaxf(__fsqrt_rn(ss), 1e-12f);
    }
    __syncthreads();

    // normalized duplicated z
    for (int i = tid; i < 64 * 32; i += 128) {
        int t = i & 31;
        float x = __fdiv_rn(zraw[i], nm[t]);
        zs2[i] = make_float2(x, x);
    }

    float best[8];
    int   bidx[8];
#pragma unroll
    for (int t = 0; t < 8; ++t) { best[t] = -1e30f; bidx[t] = 0; }

    const int t0 = warp * 8;

    for (int nt = 0; nt < NTILES; ++nt) {
        CP_WAIT0();
        __syncthreads();

        const float* ws = (nt & 1) ? (float*)(sm_ + SM_WS1) : (float*)(sm_ + SM_WS0);

        // prefetch next tile into the other buffer (safe: sync above)
        if (nt + 1 < NTILES) {
            uint32_t wsN = (nt & 1) ? (sbase + SM_WS0) : (sbase + SM_WS1);
            const char* src0 = (const char*)(g_cnormT + (size_t)(nt + 1) * KB);
            for (int i = tid; i < 2048; i += 128) {
                int c = i >> 5, q = i & 31;
                CP_ASYNC16(wsN + (c * KB + q * 4) * 4,
                           src0 + (size_t)c * NUM_EMBED * 4 + q * 16);
            }
            CP_COMMIT();
        }

        ull acc0[8], acc1[8];
#pragma unroll
        for (int t = 0; t < 8; ++t) { acc0[t] = 0ULL; acc1[t] = 0ULL; }

#pragma unroll 8
        for (int c = 0; c < 64; ++c) {
            const ull* zp = (const ull*)zs2 + (c << 5) + t0;
            ulonglong2 a0 = *(const ulonglong2*)(zp + 0);
            ulonglong2 a1 = *(const ulonglong2*)(zp + 2);
            ulonglong2 a2 = *(const ulonglong2*)(zp + 4);
            ulonglong2 a3 = *(const ulonglong2*)(zp + 6);
            ulonglong2 bb = *(const ulonglong2*)(ws + c * KB + (lane << 2));
            ull aa[8] = {a0.x, a0.y, a1.x, a1.y, a2.x, a2.y, a3.x, a3.y};
            // chain of 8 FFMA2 with the SAME b operand -> b-slot .reuse, rt->2
#pragma unroll
            for (int t = 0; t < 8; ++t) ffma2(acc0[t], aa[t], bb.x);
#pragma unroll
            for (int t = 0; t < 8; ++t) ffma2(acc1[t], aa[t], bb.y);
        }

        // running argmax update, codes ascending (strict > => first-index-wins)
        int kb = nt * KB + (lane << 2);
#pragma unroll
        for (int t = 0; t < 8; ++t) {
            float v0 = lo32(acc0[t]);
            float v1 = hi32(acc0[t]);
            float v2 = lo32(acc1[t]);
            float v3 = hi32(acc1[t]);
            if (v0 > best[t]) { best[t] = v0; bidx[t] = kb; }
            if (v1 > best[t]) { best[t] = v1; bidx[t] = kb + 1; }
            if (v2 > best[t]) { best[t] = v2; bidx[t] = kb + 2; }
            if (v3 > best[t]) { best[t] = v3; bidx[t] = kb + 3; }
        }
    }

    // lane merge: lexicographic max on (val, -idx)
#pragma unroll
    for (int t = 0; t < 8; ++t) {
        float v = best[t];
        int   i = bidx[t];
#pragma unroll
        for (int off = 16; off > 0; off >>= 1) {
            float v2 = __shfl_xor_sync(0xffffffffu, v, off);
            int   i2 = __shfl_xor_sync(0xffffffffu, i, off);
            if (v2 > v || (v2 == v && i2 < i)) { v = v2; i = i2; }
        }
        if (lane == 0) idxs[t0 + t] = i;
    }
    __syncthreads();

    // ---- fused epilogue: gather, STE output, loss partial, idx, bincount ----
    int myidx = idxs[lane];
    const float4* er = (const float4*)(ew + (size_t)myidx * ED + warp * 16);
    float4 e0 = er[0], e1 = er[1], e2 = er[2], e3 = er[3];
    float vals[16] = {e0.x, e0.y, e0.z, e0.w, e1.x, e1.y, e1.z, e1.w,
                      e2.x, e2.y, e2.z, e2.w, e3.x, e3.y, e3.z, e3.w};
    float ssq = 0.f;
#pragma unroll
    for (int j = 0; j < 16; ++j) {
        int ch = warp * 16 + j;
        float zc = zraw[ch * 32 + lane];
        float d  = vals[j] - zc;
        out_zq[(size_t)(b * 64 + ch) * 4096 + p0 + lane] = zc + d;
        ssq = fmaf(d, d, ssq);
    }
    red[tid] = ssq;
    __syncthreads();
    for (int s = 64; s > 0; s >>= 1) {
        if (tid < s) red[tid] += red[tid + s];
        __syncthreads();
    }
    if (tid == 0) g_partial[blockIdx.x] = red[0];

    if (tid < 32) {
        out_idx[tok0 + tid] = (float)idxs[tid];
        atomicAdd(&out_bin[idxs[tid]], 1.0f);
    }
}

// ---------------- K4: deterministic loss finalize ----------------
__global__ void k4_loss(float* __restrict__ out_loss) {
    int lane = threadIdx.x;
    float s = 0.f;
    for (int i = lane * 32; i < lane * 32 + 32; ++i) s += g_partial[i];
#pragma unroll
    for (int off = 16; off > 0; off >>= 1)
        s += __shfl_xor_sync(0xffffffffu, s, off);
    if (lane == 0) {
        float m = s / 2097152.0f;
        out_loss[0] = 0.25f * m + m;
    }
}

extern "C" void kernel_launch(void* const* d_in, const int* in_sizes, int n_in,
                              void* d_out, int out_size) {
    const float* z  = (const float*)d_in[0];
    const float* ew = (const float*)d_in[1];
    float* out      = (float*)d_out;

    float* out_zq   = out;
    float* out_loss = out + OFF_LOSS;
    float* out_idx  = out + OFF_IDX;
    float* out_bin  = out + OFF_BIN;

    cudaMemsetAsync(out_bin, 0, NUM_EMBED * sizeof(float));

    k1_normalize<<<NUM_EMBED / 256, 256>>>(ew);

    cudaFuncSetAttribute(k2_all, cudaFuncAttributeMaxDynamicSharedMemorySize, SM_TOT);
    k2_all<<<NBLK, 128, SM_TOT>>>(z, ew, out_zq, out_idx, out_bin);

    k4_loss<<<1, 32>>>(out_loss);
}